// round 14
// baseline (speedup 1.0000x reference)
#include <cuda_runtime.h>
#include <cuda_bf16.h>
#include <cuda_fp16.h>
#include <cstdint>

// Problem constants
#define BB 8
#define TT 128
#define SS 512
#define DD 128
#define CLUSTER 16
#define SSLICE (SS / CLUSTER)   // 32 encoder rows per rank
#define DSLICE (DD / CLUSTER)   // 8 output dims per rank
#define NTHR 256
#define NWARP 8

// Scratch (allocation-free rule: __device__ globals)
__device__ float g_HU[BB * SS * DD];   // H @ Ua, [B,S,D]
__device__ float g_XG[BB * TT * 512];  // x@W + bias for 4 gates (i,f,c,o), [B,T,512]

__device__ __forceinline__ float4 ldg4(const float* p) {
    return __ldg(reinterpret_cast<const float4*>(p));
}
__device__ __forceinline__ uint32_t smem_u32(const void* p) {
    uint32_t a;
    asm("{ .reg .u64 t; cvta.to.shared.u64 t, %1; cvt.u32.u64 %0, t; }" : "=r"(a) : "l"(p));
    return a;
}
// st.async a float to the SAME smem offset on cluster CTA `rank`, completing
// tx bytes on that rank's mbarrier (inline mapa — proven pattern).
__device__ __forceinline__ void st_async_remote(uint32_t laddr, uint32_t lmbar,
                                                uint32_t rank, float v) {
    uint32_t ra, rb;
    asm volatile("mapa.shared::cluster.u32 %0, %1, %2;" : "=r"(ra) : "r"(laddr), "r"(rank));
    asm volatile("mapa.shared::cluster.u32 %0, %1, %2;" : "=r"(rb) : "r"(lmbar), "r"(rank));
    asm volatile("st.async.shared::cluster.mbarrier::complete_tx::bytes.b32 [%0], %1, [%2];"
                 :: "r"(ra), "r"(__float_as_uint(v)), "r"(rb) : "memory");
}
// 16-byte packed variant: 4 floats per DSMEM message.
__device__ __forceinline__ void st_async_remote_v4(uint32_t laddr, uint32_t lmbar,
                                                   uint32_t rank, float a, float b,
                                                   float c, float d) {
    uint32_t ra, rb;
    asm volatile("mapa.shared::cluster.u32 %0, %1, %2;" : "=r"(ra) : "r"(laddr), "r"(rank));
    asm volatile("mapa.shared::cluster.u32 %0, %1, %2;" : "=r"(rb) : "r"(lmbar), "r"(rank));
    asm volatile("st.async.shared::cluster.mbarrier::complete_tx::bytes.v4.b32 "
                 "[%0], {%1, %2, %3, %4}, [%5];"
                 :: "r"(ra), "r"(__float_as_uint(a)), "r"(__float_as_uint(b)),
                    "r"(__float_as_uint(c)), "r"(__float_as_uint(d)), "r"(rb) : "memory");
}
__device__ __forceinline__ void mbar_init(uint32_t addr, uint32_t count) {
    asm volatile("mbarrier.init.shared.b64 [%0], %1;" :: "r"(addr), "r"(count) : "memory");
}
__device__ __forceinline__ void mbar_expect_tx(uint32_t addr, uint32_t bytes) {
    asm volatile("mbarrier.arrive.expect_tx.shared.b64 _, [%0], %1;"
                 :: "r"(addr), "r"(bytes) : "memory");
}
__device__ __forceinline__ void mbar_wait(uint32_t addr, uint32_t parity) {
    uint32_t done;
    asm volatile(
        "{\n\t.reg .pred p;\n\t"
        "mbarrier.try_wait.parity.acquire.cta.shared::cta.b64 p, [%1], %2;\n\t"
        "selp.b32 %0, 1, 0, p;\n\t}"
        : "=r"(done) : "r"(addr), "r"(parity) : "memory");
    if (!done) {
        asm volatile(
            "{\n\t.reg .pred P1;\n\t"
            "WL_%=:\n\t"
            "mbarrier.try_wait.parity.acquire.cta.shared::cta.b64 P1, [%0], %1, 0x989680;\n\t"
            "@P1 bra.uni WD_%=;\n\t"
            "bra.uni WL_%=;\n\t"
            "WD_%=:\n\t}"
            :: "r"(addr), "r"(parity) : "memory");
    }
}
#define CLUSTER_SYNC() do { \
    asm volatile("barrier.cluster.arrive.aligned;" ::: "memory"); \
    asm volatile("barrier.cluster.wait.aligned;"   ::: "memory"); \
} while (0)

// ---------------------------------------------------------------------------
// Merged precompute kernel (one launch, full chip):
//   blocks [0,512):    HU[b,s,e] = sum_d H[b,s,d] * Ua[d,e]   (8 rows/block)
//   blocks [512,1024): XG[row, g*128+c] = b_g[c] + sum_k x[row,k]*W_g[k,c]
// ---------------------------------------------------------------------------
__global__ __launch_bounds__(128) void pre_kernel(
    const float* __restrict__ H, const float* __restrict__ Ua,
    const float* __restrict__ x,
    const float* __restrict__ Wi, const float* __restrict__ Wf,
    const float* __restrict__ Wc, const float* __restrict__ Wo,
    const float* __restrict__ bi, const float* __restrict__ bf,
    const float* __restrict__ bc, const float* __restrict__ bo) {
    __shared__ __align__(16) float sA[8 * DD];
    const int tid = threadIdx.x;
    const int blk = blockIdx.x;

    const float* Asrc;
    const float* W;
    float bias = 0.f;
    float* dst;
    int dstride;
    if (blk < 512) {
        Asrc = H + (size_t)blk * 8 * DD;
        W = Ua;
        dst = g_HU + (size_t)blk * 8 * DD;
        dstride = DD;
    } else {
        const int idx = blk - 512;
        const int g = idx >> 7, rb = idx & 127;
        Asrc = x + (size_t)rb * 8 * DD;
        W = (g == 0) ? Wi : (g == 1) ? Wf : (g == 2) ? Wc : Wo;
        const float* bb = (g == 0) ? bi : (g == 1) ? bf : (g == 2) ? bc : bo;
        bias = __ldg(bb + tid);
        dst = g_XG + (size_t)rb * 8 * 512 + g * DD;
        dstride = 512;
    }
    #pragma unroll
    for (int i = 0; i < 8; i++) sA[i * DD + tid] = __ldg(Asrc + i * DD + tid);
    __syncthreads();

    float acc[8];
    #pragma unroll
    for (int r = 0; r < 8; r++) acc[r] = bias;
    #pragma unroll 4
    for (int k0 = 0; k0 < DD; k0 += 4) {
        const float w0 = __ldg(W + (k0 + 0) * DD + tid);
        const float w1 = __ldg(W + (k0 + 1) * DD + tid);
        const float w2 = __ldg(W + (k0 + 2) * DD + tid);
        const float w3 = __ldg(W + (k0 + 3) * DD + tid);
        #pragma unroll
        for (int r = 0; r < 8; r++) {
            const float4 a = *reinterpret_cast<const float4*>(&sA[r * DD + k0]);
            acc[r] += a.x * w0 + a.y * w1 + a.z * w2 + a.w * w3;
        }
    }
    #pragma unroll
    for (int r = 0; r < 8; r++) dst[r * dstride + tid] = acc[r];
}

// ---------------------------------------------------------------------------
// Recurrent kernel: 8 clusters x 16 CTAs (non-portable cluster size),
// ONE batch per cluster, 256 threads. 128 SMs active (vs 64 at cluster=8).
// Rank r:
//   - attention over encoder rows [32r, 32r+32)   (HU, H slices in smem)
//   - ALL FOUR gates for output dims [8r, 8r+8): warp wp owns dim 8r+wp,
//     its 4 gates living in the four 8-lane groups (U, C cols in registers)
//     -> LSTM update LOCAL; h_new broadcast via st.async into every rank's
//        sh, completing h_mbar.
// f16x2 tanh in the score kernel. Final-step broadcast skipped + trailing
// CLUSTER_SYNC (exit protocol from the R12 fix).
// ---------------------------------------------------------------------------
// dynamic smem layout (floats):
//   sHU   [0    ,  4096)   HU slice (32 x 128)
//   sH    [4096 ,  8192)   H slice
//   sh    [8192 ,  8320)   h state (filled via st.async h-broadcast)
//   sq    [8320 ,  8448)
//   sctx  [8448 ,  8576)   UNNORMALIZED ctx sum
//   part  [8576 ,  9600)   8 x 128 ctx warp partials
//   zred  [9600 ,  9608)
//   ctxbuf[9608 , 11720)   16 x 132 mailbox (ctx[128] + z at [128])
//   mbars [11720, 11724)   2 x u64 (ctx, h)
//   invZ  [11724, 11725)
#define SM_FLOATS 11728

__global__ __launch_bounds__(NTHR, 1) __cluster_dims__(CLUSTER, 1, 1)
void rec_kernel(const float* __restrict__ H, const float* __restrict__ init,
                const float* __restrict__ Wa, const float* __restrict__ v,
                const float* __restrict__ Ui, const float* __restrict__ Ci,
                const float* __restrict__ Uf, const float* __restrict__ Cf,
                const float* __restrict__ Uc, const float* __restrict__ Cc,
                const float* __restrict__ Uo, const float* __restrict__ Co,
                float* __restrict__ out) {
    extern __shared__ __align__(16) float dsm[];
    float* sHU    = dsm;
    float* sHs    = dsm + 4096;
    float* sh     = dsm + 8192;
    float* sq     = dsm + 8320;
    float* sctx   = dsm + 8448;
    float* part   = dsm + 8576;
    float* zred   = dsm + 9600;
    float* ctxbuf = dsm + 9608;
    float* mbars  = dsm + 11720;
    float* s_invZ = dsm + 11724;

    const int tid  = threadIdx.x;
    const int lane = tid & 31;
    const int wp   = tid >> 5;           // 0..7
    const int b    = blockIdx.x >> 4;    // batch
    const int rk   = blockIdx.x & 15;    // cluster rank

    const uint32_t ctx_mbar = smem_u32(&mbars[0]);
    const uint32_t h_mbar   = smem_u32(&mbars[2]);

    // ---------------- prologue ----------------
    if (tid == 0) {
        mbar_init(ctx_mbar, 1);
        mbar_init(h_mbar, 1);
        asm volatile("fence.mbarrier_init.release.cluster;" ::: "memory");
    }
    {
        const float4* HUsrc = (const float4*)(g_HU + (size_t)(b * SS + rk * SSLICE) * DD);
        const float4* Hsrc  = (const float4*)(H    + (size_t)(b * SS + rk * SSLICE) * DD);
        float4* dHU = (float4*)sHU;
        float4* dH  = (float4*)sHs;
        #pragma unroll
        for (int i = 0; i < 4; i++) {
            dHU[tid + i * NTHR] = HUsrc[tid + i * NTHR];
            dH[tid + i * NTHR]  = Hsrc[tid + i * NTHR];
        }
    }

    // v cached per-lane: f16x2 pairs for the tanh dot
    const float4 vreg = ldg4(v + 4 * lane);
    const __half2 v01 = __floats2half2_rn(vreg.x, vreg.y);
    const __half2 v23 = __floats2half2_rn(vreg.z, vreg.w);

    // P1 layout: warp wp -> q cols [16wp,16wp+16); col = 16wp+(lane&15);
    // k-part qp = lane>>4 (2 parts), k = qp + 2*kk.
    const int qcol = (wp << 4) + (lane & 15);
    const int qp   = lane >> 4;
    float waReg[64];
    #pragma unroll
    for (int kk = 0; kk < 64; kk++)
        waReg[kk] = __ldg(Wa + (qp + 2 * kk) * DD + qcol);

    // gate layout: rank rk owns dims [8rk, 8rk+8), all 4 gates.
    // cidx = tid>>3 in [0,32): warp wp covers cidx 4wp..4wp+3 = dim wp's 4 gates.
    // ggate = (lane>>3)&3; dloc = wp; dcol = 8rk + wp.
    // k-part gp = tid&7 (8 parts), k = gp + 8*kk, 16 k each.
    const int ggate = (lane >> 3) & 3;
    const int dcol  = DSLICE * rk + wp;
    const int gp    = tid & 7;
    const float* Ug = (ggate == 0) ? Ui : (ggate == 1) ? Uf : (ggate == 2) ? Uc : Uo;
    const float* Cg = (ggate == 0) ? Ci : (ggate == 1) ? Cf : (ggate == 2) ? Cc : Co;
    float Ureg[16], Creg[16];
    #pragma unroll
    for (int kk = 0; kk < 16; kk++) {
        const int k = gp + 8 * kk;
        Ureg[kk] = __ldg(Ug + k * DD + dcol);
        Creg[kk] = __ldg(Cg + k * DD + dcol);
    }

    const float* XGb = g_XG + (size_t)b * TT * 512;

    // Mailbox slot addresses (same smem offsets cluster-wide; sender-indexed).
    const uint32_t ctx_addr = (tid < DD) ? smem_u32(&ctxbuf[rk * 132 + tid]) : 0u;
    const uint32_t zsl_addr = smem_u32(&ctxbuf[rk * 132 + 128]);

    // h owner: lane 0 of each warp owns dim dme = 8rk + wp.
    const int dme = DSLICE * rk + wp;
    const uint32_t h_addr = smem_u32(&sh[dme]);
    const bool h_owner = (lane == 0);

    // local cell state (valid on owner lanes)
    float cell = __ldg(init + BB * DD + b * DD + dme);
    const float h0 = __ldg(init + b * DD + dme);

    __syncthreads();
    CLUSTER_SYNC();   // mbarriers + smem ready on every rank

    // seed phase 0 of h_mbar with the initial h broadcast
    if (tid == 0) mbar_expect_tx(h_mbar, DD * 4);
    if (h_owner) {
        #pragma unroll
        for (int q = 0; q < CLUSTER; q++)
            st_async_remote(h_addr, h_mbar, (uint32_t)q, h0);
    }

    for (int t = 0; t < TT; t++) {
        const uint32_t parity = (uint32_t)(t & 1);
        // h for this step (written by all ranks' broadcasts) is complete:
        mbar_wait(h_mbar, parity);
        if (tid == 0) {
            mbar_expect_tx(ctx_mbar, CLUSTER * 129 * 4); // this step's ctx
            if (t + 1 < TT) mbar_expect_tx(h_mbar, DD * 4); // next phase's h
        }
        // prefetch this step's x-gate contribution
        const float xg = __ldg(XGb + t * 512 + ggate * DD + dcol);

        // ---------- P1: q = h @ Wa (regs) + hoisted h@U gate partial ----------
        float hu;
        {
            float accq = 0.f, huv = 0.f;
            #pragma unroll
            for (int kk = 0; kk < 64; kk++) accq += sh[qp + 2 * kk] * waReg[kk];
            #pragma unroll
            for (int kk = 0; kk < 16; kk++) huv += sh[gp + 8 * kk] * Ureg[kk];
            hu = huv;
            accq += __shfl_xor_sync(0xffffffffu, accq, 16);
            if (lane < 16) sq[(wp << 4) + lane] = accq;
        }
        __syncthreads();  // A

        // ---------- P2: scores (f16x2 tanh) -> exp -> ctx partial over the
        //            32-row slice. no-max softmax: |score| <= sum|v| ~ 5. ----------
        {
            const float4 q4 = *reinterpret_cast<const float4*>(&sq[lane * 4]);
            float4 ctx4 = make_float4(0.f, 0.f, 0.f, 0.f);
            float zp = 0.f;
            #pragma unroll
            for (int i = 0; i < 4; i++) {
                const int s = wp + (i << 3);      // rows 0..31
                const float4 hu4 = *reinterpret_cast<const float4*>(&sHU[s * DD + lane * 4]);
                const __half2 a01 = __floats2half2_rn(hu4.x + q4.x, hu4.y + q4.y);
                const __half2 a23 = __floats2half2_rn(hu4.z + q4.z, hu4.w + q4.w);
                uint32_t t01, t23;
                asm("tanh.approx.f16x2 %0, %1;"
                    : "=r"(t01) : "r"(*reinterpret_cast<const uint32_t*>(&a01)));
                asm("tanh.approx.f16x2 %0, %1;"
                    : "=r"(t23) : "r"(*reinterpret_cast<const uint32_t*>(&a23)));
                const __half2 m = __hfma2(*reinterpret_cast<const __half2*>(&t01), v01,
                                  __hmul2(*reinterpret_cast<const __half2*>(&t23), v23));
                float sc = __low2float(m) + __high2float(m);
                #pragma unroll
                for (int o = 16; o > 0; o >>= 1) sc += __shfl_xor_sync(0xffffffffu, sc, o);
                const float e = __expf(sc);
                zp += e;
                const float4 h4 = *reinterpret_cast<const float4*>(&sHs[s * DD + lane * 4]);
                ctx4.x += e * h4.x; ctx4.y += e * h4.y;
                ctx4.z += e * h4.z; ctx4.w += e * h4.w;
            }
            *reinterpret_cast<float4*>(&part[wp * DD + lane * 4]) = ctx4;
            if (lane == 0) zred[wp] = zp;
        }
        __syncthreads();  // B

        // ---------- exchange: packed (ctx_r, z_r) -> all 16 ranks ----------
        if (tid < DD) {
            float c = 0.f;
            #pragma unroll
            for (int w = 0; w < NWARP; w++) c += part[w * DD + tid];
            const float c1 = __shfl_down_sync(0xffffffffu, c, 1);
            const float c2 = __shfl_down_sync(0xffffffffu, c, 2);
            const float c3 = __shfl_down_sync(0xffffffffu, c, 3);
            if ((lane & 3) == 0) {
                #pragma unroll
                for (int q = 0; q < CLUSTER; q++)
                    st_async_remote_v4(ctx_addr, ctx_mbar, (uint32_t)q, c, c1, c2, c3);
            }
        } else if (wp == 4 && lane < 16) {
            // z reduce: lanes 0-15 each read zred[lane&7]; xor tree over the
            // 8-groups gives every lane the total; each sends to rank = lane.
            float zz = zred[lane & 7];
            zz += __shfl_xor_sync(0x0000ffffu, zz, 4);
            zz += __shfl_xor_sync(0x0000ffffu, zz, 2);
            zz += __shfl_xor_sync(0x0000ffffu, zz, 1);
            st_async_remote(zsl_addr, ctx_mbar, (uint32_t)lane, zz);
        }
        mbar_wait(ctx_mbar, parity);

        // ---------- combine: sctx = sum_r ctx_r (unnormalized); invZ once ----------
        if (tid < DD) {
            float c = 0.f;
            #pragma unroll
            for (int q = 0; q < CLUSTER; q++) c += ctxbuf[q * 132 + tid];
            sctx[tid] = c;
        } else if (tid == DD) {
            float Z = 0.f;
            #pragma unroll
            for (int q = 0; q < CLUSTER; q++) Z += ctxbuf[q * 132 + 128];
            s_invZ[0] = 1.f / Z;
        }
        __syncthreads();  // C

        // ---------- P4: dim wp's 4 gates; LOCAL LSTM update;
        //             broadcast h_new into every rank's sh ----------
        {
            const float invZ = s_invZ[0];
            float acc = 0.f;
            #pragma unroll
            for (int kk = 0; kk < 16; kk++) acc += sctx[gp + 8 * kk] * Creg[kk];
            float p = hu + acc * invZ;
            p += __shfl_xor_sync(0xffffffffu, p, 1);
            p += __shfl_xor_sync(0xffffffffu, p, 2);
            p += __shfl_xor_sync(0xffffffffu, p, 4);
            const float pre = p + xg;
            const float act = (ggate == 2) ? tanhf(pre) : 1.f / (1.f + __expf(-pre));
            // gates of dim wp live at lanes 0 (i), 8 (f), 16 (c), 24 (o)
            const float ig = __shfl_sync(0xffffffffu, act, 0);
            const float fg = __shfl_sync(0xffffffffu, act, 8);
            const float gw = __shfl_sync(0xffffffffu, act, 16);
            const float og = __shfl_sync(0xffffffffu, act, 24);
            if (h_owner) {
                cell = fg * cell + ig * gw;
                const float hn = og * tanhf(cell);
                out[(size_t)(b * TT + t) * DD + dme] = hn;
                if (t + 1 < TT) {   // final h never consumed -> never sent
                    #pragma unroll
                    for (int q = 0; q < CLUSTER; q++)
                        st_async_remote(h_addr, h_mbar, (uint32_t)q, hn);
                }
            }
        }
        // no barrier here: next iteration's h_mbar wait orders everything.
    }

    // quiesce the cluster before any CTA retires (no in-flight remote writes)
    CLUSTER_SYNC();
}

// ---------------------------------------------------------------------------
extern "C" void kernel_launch(void* const* d_in, const int* in_sizes, int n_in,
                              void* d_out, int out_size) {
    const float* x    = (const float*)d_in[0];
    const float* H    = (const float*)d_in[1];
    const float* init = (const float*)d_in[2];
    const float* Wa   = (const float*)d_in[3];
    const float* Ua   = (const float*)d_in[4];
    const float* v    = (const float*)d_in[5];
    const float* Wi   = (const float*)d_in[6];
    const float* Ui   = (const float*)d_in[7];
    const float* Ci   = (const float*)d_in[8];
    const float* bi   = (const float*)d_in[9];
    const float* Wf   = (const float*)d_in[10];
    const float* Uf   = (const float*)d_in[11];
    const float* Cf   = (const float*)d_in[12];
    const float* bf   = (const float*)d_in[13];
    const float* Wc   = (const float*)d_in[14];
    const float* Uc   = (const float*)d_in[15];
    const float* Cc   = (const float*)d_in[16];
    const float* bc   = (const float*)d_in[17];
    const float* Wo   = (const float*)d_in[18];
    const float* Uo   = (const float*)d_in[19];
    const float* Co   = (const float*)d_in[20];
    const float* bo   = (const float*)d_in[21];
    float* out = (float*)d_out;

    static bool attr_set = false;
    if (!attr_set) {
        cudaFuncSetAttribute(rec_kernel,
                             cudaFuncAttributeMaxDynamicSharedMemorySize,
                             SM_FLOATS * sizeof(float));
        cudaFuncSetAttribute(rec_kernel,
                             cudaFuncAttributeNonPortableClusterSizeAllowed, 1);
        attr_set = true;
    }

    pre_kernel<<<1024, 128>>>(H, Ua, x, Wi, Wf, Wc, Wo, bi, bf, bc, bo);
    rec_kernel<<<BB * CLUSTER, NTHR, SM_FLOATS * sizeof(float)>>>(
        H, init, Wa, v, Ui, Ci, Uf, Cf, Uc, Cc, Uo, Co, out);
}

// round 16
// speedup vs baseline: 1.9243x; 1.9243x over previous
#include <cuda_runtime.h>
#include <cuda_bf16.h>
#include <cuda_fp16.h>
#include <cstdint>

// Problem constants
#define BB 8
#define TT 128
#define SS 512
#define DD 128
#define CLUSTER 8
#define SSLICE (SS / CLUSTER)   // 64 encoder rows per rank
#define DSLICE (DD / CLUSTER)   // 16 output dims per rank
#define NTHR 256
#define NWARP 8

// Scratch (allocation-free rule: __device__ globals)
__device__ __half g_HUh[BB * SS * DD];  // H @ Ua in f16, [B,S,D]
__device__ float  g_XG[BB * TT * 512];  // x@W + bias for 4 gates (i,f,c,o)

__device__ __forceinline__ float4 ldg4(const float* p) {
    return __ldg(reinterpret_cast<const float4*>(p));
}
__device__ __forceinline__ uint32_t smem_u32(const void* p) {
    uint32_t a;
    asm("{ .reg .u64 t; cvta.to.shared.u64 t, %1; cvt.u32.u64 %0, t; }" : "=r"(a) : "l"(p));
    return a;
}
// st.async a float to the SAME smem offset on cluster CTA `rank`, completing
// tx bytes on that rank's mbarrier (inline mapa — proven pattern).
__device__ __forceinline__ void st_async_remote(uint32_t laddr, uint32_t lmbar,
                                                uint32_t rank, float v) {
    uint32_t ra, rb;
    asm volatile("mapa.shared::cluster.u32 %0, %1, %2;" : "=r"(ra) : "r"(laddr), "r"(rank));
    asm volatile("mapa.shared::cluster.u32 %0, %1, %2;" : "=r"(rb) : "r"(lmbar), "r"(rank));
    asm volatile("st.async.shared::cluster.mbarrier::complete_tx::bytes.b32 [%0], %1, [%2];"
                 :: "r"(ra), "r"(__float_as_uint(v)), "r"(rb) : "memory");
}
// 16-byte packed variant: 4 floats per DSMEM message.
__device__ __forceinline__ void st_async_remote_v4(uint32_t laddr, uint32_t lmbar,
                                                   uint32_t rank, float a, float b,
                                                   float c, float d) {
    uint32_t ra, rb;
    asm volatile("mapa.shared::cluster.u32 %0, %1, %2;" : "=r"(ra) : "r"(laddr), "r"(rank));
    asm volatile("mapa.shared::cluster.u32 %0, %1, %2;" : "=r"(rb) : "r"(lmbar), "r"(rank));
    asm volatile("st.async.shared::cluster.mbarrier::complete_tx::bytes.v4.b32 "
                 "[%0], {%1, %2, %3, %4}, [%5];"
                 :: "r"(ra), "r"(__float_as_uint(a)), "r"(__float_as_uint(b)),
                    "r"(__float_as_uint(c)), "r"(__float_as_uint(d)), "r"(rb) : "memory");
}
__device__ __forceinline__ void mbar_init(uint32_t addr, uint32_t count) {
    asm volatile("mbarrier.init.shared.b64 [%0], %1;" :: "r"(addr), "r"(count) : "memory");
}
__device__ __forceinline__ void mbar_expect_tx(uint32_t addr, uint32_t bytes) {
    asm volatile("mbarrier.arrive.expect_tx.shared.b64 _, [%0], %1;"
                 :: "r"(addr), "r"(bytes) : "memory");
}
__device__ __forceinline__ void mbar_wait(uint32_t addr, uint32_t parity) {
    uint32_t done;
    asm volatile(
        "{\n\t.reg .pred p;\n\t"
        "mbarrier.try_wait.parity.acquire.cta.shared::cta.b64 p, [%1], %2;\n\t"
        "selp.b32 %0, 1, 0, p;\n\t}"
        : "=r"(done) : "r"(addr), "r"(parity) : "memory");
    if (!done) {
        asm volatile(
            "{\n\t.reg .pred P1;\n\t"
            "WL_%=:\n\t"
            "mbarrier.try_wait.parity.acquire.cta.shared::cta.b64 P1, [%0], %1, 0x989680;\n\t"
            "@P1 bra.uni WD_%=;\n\t"
            "bra.uni WL_%=;\n\t"
            "WD_%=:\n\t}"
            :: "r"(addr), "r"(parity) : "memory");
    }
}
#define CLUSTER_SYNC() do { \
    asm volatile("barrier.cluster.arrive.aligned;" ::: "memory"); \
    asm volatile("barrier.cluster.wait.aligned;"   ::: "memory"); \
} while (0)

// ---------------------------------------------------------------------------
// Merged precompute kernel (one launch, full chip):
//   blocks [0,512):    HU[b,s,e] = sum_d H[b,s,d] * Ua[d,e]  -> f16 g_HUh
//   blocks [512,1024): XG[row, g*128+c] = b_g[c] + sum_k x[row,k]*W_g[k,c]
// ---------------------------------------------------------------------------
__global__ __launch_bounds__(128) void pre_kernel(
    const float* __restrict__ H, const float* __restrict__ Ua,
    const float* __restrict__ x,
    const float* __restrict__ Wi, const float* __restrict__ Wf,
    const float* __restrict__ Wc, const float* __restrict__ Wo,
    const float* __restrict__ bi, const float* __restrict__ bf,
    const float* __restrict__ bc, const float* __restrict__ bo) {
    __shared__ __align__(16) float sA[8 * DD];
    const int tid = threadIdx.x;
    const int blk = blockIdx.x;

    const float* Asrc;
    const float* W;
    float bias = 0.f;
    float* dst = nullptr;
    __half* dsth = nullptr;
    int dstride = 0;
    const bool is_hu = (blk < 512);
    if (is_hu) {
        Asrc = H + (size_t)blk * 8 * DD;
        W = Ua;
        dsth = g_HUh + (size_t)blk * 8 * DD;
    } else {
        const int idx = blk - 512;
        const int g = idx >> 7, rb = idx & 127;
        Asrc = x + (size_t)rb * 8 * DD;
        W = (g == 0) ? Wi : (g == 1) ? Wf : (g == 2) ? Wc : Wo;
        const float* bb = (g == 0) ? bi : (g == 1) ? bf : (g == 2) ? bc : bo;
        bias = __ldg(bb + tid);
        dst = g_XG + (size_t)rb * 8 * 512 + g * DD;
        dstride = 512;
    }
    #pragma unroll
    for (int i = 0; i < 8; i++) sA[i * DD + tid] = __ldg(Asrc + i * DD + tid);
    __syncthreads();

    float acc[8];
    #pragma unroll
    for (int r = 0; r < 8; r++) acc[r] = bias;
    #pragma unroll 4
    for (int k0 = 0; k0 < DD; k0 += 4) {
        const float w0 = __ldg(W + (k0 + 0) * DD + tid);
        const float w1 = __ldg(W + (k0 + 1) * DD + tid);
        const float w2 = __ldg(W + (k0 + 2) * DD + tid);
        const float w3 = __ldg(W + (k0 + 3) * DD + tid);
        #pragma unroll
        for (int r = 0; r < 8; r++) {
            const float4 a = *reinterpret_cast<const float4*>(&sA[r * DD + k0]);
            acc[r] += a.x * w0 + a.y * w1 + a.z * w2 + a.w * w3;
        }
    }
    if (is_hu) {
        #pragma unroll
        for (int r = 0; r < 8; r++) dsth[r * DD + tid] = __float2half(acc[r]);
    } else {
        #pragma unroll
        for (int r = 0; r < 8; r++) dst[r * dstride + tid] = acc[r];
    }
}

// ---------------------------------------------------------------------------
// Recurrent kernel: 8 clusters x 8 CTAs, ONE batch per cluster, 256 threads.
// Rank r:
//   - attention over encoder rows [64r, 64r+64)   (HU in f16, H in f32 smem)
//   - ALL FOUR gates for output dims [16r, 16r+16) (U, C cols in registers)
//     -> LSTM update LOCAL; h_new broadcast via st.async (one shuffle + 8
//        parallel lane-sends) into every rank's sh, completing h_mbar.
// f16x2 tanh with f16-resident HU. Fix vs the hanging version: the SEED
// broadcast's shuffle is hoisted OUT of the divergent branch (full-mask
// shfl inside a half-warp branch is UB and hung the kernel).
// ---------------------------------------------------------------------------
// dynamic smem layout (float-slot offsets):
//   sHUh  [0    ,  4096)   HU slice as half2 (64 x 64 u32)
//   sH    [4096 , 12288)   H slice f32
//   sh    [12288, 12416)   h state (filled via st.async h-broadcast)
//   sq    [12416, 12544)
//   sctx  [12544, 12672)   UNNORMALIZED ctx sum
//   part  [12672, 13696)   8 x 128 ctx warp partials
//   zred  [13696, 13704)
//   ctxbuf[13704, 14760)   8 x 132 mailbox (ctx[128] + z at [128])
//   mbars [14760, 14764)   2 x u64 (ctx, h)
//   invZ  [14764, 14765)
#define SM_FLOATS 14768

__global__ __launch_bounds__(NTHR, 1) __cluster_dims__(CLUSTER, 1, 1)
void rec_kernel(const float* __restrict__ H, const float* __restrict__ init,
                const float* __restrict__ Wa, const float* __restrict__ v,
                const float* __restrict__ Ui, const float* __restrict__ Ci,
                const float* __restrict__ Uf, const float* __restrict__ Cf,
                const float* __restrict__ Uc, const float* __restrict__ Cc,
                const float* __restrict__ Uo, const float* __restrict__ Co,
                float* __restrict__ out) {
    extern __shared__ __align__(16) float dsm[];
    uint32_t* sHUh  = reinterpret_cast<uint32_t*>(dsm);   // half2 units
    float* sHs    = dsm + 4096;
    float* sh     = dsm + 12288;
    float* sq     = dsm + 12416;
    float* sctx   = dsm + 12544;
    float* part   = dsm + 12672;
    float* zred   = dsm + 13696;
    float* ctxbuf = dsm + 13704;
    float* mbars  = dsm + 14760;
    float* s_invZ = dsm + 14764;

    const int tid  = threadIdx.x;
    const int lane = tid & 31;
    const int wp   = tid >> 5;          // 0..7
    const int b    = blockIdx.x >> 3;   // batch
    const int rk   = blockIdx.x & 7;    // cluster rank

    const uint32_t ctx_mbar = smem_u32(&mbars[0]);
    const uint32_t h_mbar   = smem_u32(&mbars[2]);

    // ---------------- prologue ----------------
    if (tid == 0) {
        mbar_init(ctx_mbar, 1);
        mbar_init(h_mbar, 1);
        asm volatile("fence.mbarrier_init.release.cluster;" ::: "memory");
    }
    {
        // HU slice (f16): 64 rows x 128 halves = 1024 uint4
        const uint4* HUsrc = (const uint4*)(g_HUh + (size_t)(b * SS + rk * SSLICE) * DD);
        uint4* dHU = (uint4*)sHUh;
        #pragma unroll
        for (int i = 0; i < 4; i++) dHU[tid + i * NTHR] = HUsrc[tid + i * NTHR];
        // H slice (f32): 2048 float4
        const float4* Hsrc = (const float4*)(H + (size_t)(b * SS + rk * SSLICE) * DD);
        float4* dH = (float4*)sHs;
        #pragma unroll
        for (int i = 0; i < 8; i++) dH[tid + i * NTHR] = Hsrc[tid + i * NTHR];
    }

    // v cached per-lane: f16x2 pairs for the tanh dot
    const float4 vreg = ldg4(v + 4 * lane);
    const __half2 v01 = __floats2half2_rn(vreg.x, vreg.y);
    const __half2 v23 = __floats2half2_rn(vreg.z, vreg.w);

    // P1 layout: warp wp -> q cols [16wp,16wp+16); col = 16wp+(lane&15);
    // k-part qp = lane>>4 (2 parts), k = qp + 2*kk.
    const int qcol = (wp << 4) + (lane & 15);
    const int qp   = lane >> 4;
    float waReg[64];
    #pragma unroll
    for (int kk = 0; kk < 64; kk++)
        waReg[kk] = __ldg(Wa + (qp + 2 * kk) * DD + qcol);

    // gate layout: rank rk owns dims [16rk, 16rk+16), all 4 gates.
    // cidx = tid>>2 in [0,64): gate = cidx&3, dloc = cidx>>2, dcol = 16rk+dloc.
    // k-part gp = tid&3 (4 parts), k = gp + 4*kk.
    const int cidx = tid >> 2;
    const int ggate = cidx & 3;
    const int dloc  = cidx >> 2;
    const int dcol  = DSLICE * rk + dloc;
    const int gp    = tid & 3;
    const float* Ug = (ggate == 0) ? Ui : (ggate == 1) ? Uf : (ggate == 2) ? Uc : Uo;
    const float* Cg = (ggate == 0) ? Ci : (ggate == 1) ? Cf : (ggate == 2) ? Cc : Co;
    float Ureg[32], Creg[32];
    #pragma unroll
    for (int kk = 0; kk < 32; kk++) {
        const int k = gp + 4 * kk;
        Ureg[kk] = __ldg(Ug + k * DD + dcol);
        Creg[kk] = __ldg(Cg + k * DD + dcol);
    }

    const float* XGb = g_XG + (size_t)b * TT * 512;

    // Mailbox slot addresses (same smem offsets cluster-wide; sender-indexed).
    const uint32_t ctx_addr = (tid < DD) ? smem_u32(&ctxbuf[rk * 132 + tid]) : 0u;
    const uint32_t zsl_addr = smem_u32(&ctxbuf[rk * 132 + 128]);

    // h ownership: within warp wp, half-group (lane>>4) covers dim
    // dme = 16rk + 2wp + (lane>>4); lanes 0/16 own cell state; the 8 low
    // lanes of each half-group spread the broadcast (rank = lane&7).
    const int dme = DSLICE * rk + 2 * wp + (lane >> 4);
    const uint32_t h_addr = smem_u32(&sh[dme]);
    const bool h_owner = ((lane & 15) == 0);

    // local cell state (valid on owner lanes)
    float cell = __ldg(init + BB * DD + b * DD + dme);
    const float h0 = __ldg(init + b * DD + dme);

    __syncthreads();
    CLUSTER_SYNC();   // mbarriers + smem ready on every rank

    // seed phase 0 of h_mbar with the initial h broadcast (spread over lanes).
    // NOTE: shuffle executed by ALL lanes (hoisted out of the guard).
    if (tid == 0) mbar_expect_tx(h_mbar, DD * 4);
    {
        const float h0b = __shfl_sync(0xffffffffu, h0, lane & 16);
        if ((lane & 15) < 8)
            st_async_remote(h_addr, h_mbar, (uint32_t)(lane & 7), h0b);
    }

    for (int t = 0; t < TT; t++) {
        const uint32_t parity = (uint32_t)(t & 1);
        // h for this step (written by all ranks' broadcasts) is complete:
        mbar_wait(h_mbar, parity);
        if (tid == 0) {
            mbar_expect_tx(ctx_mbar, CLUSTER * 129 * 4); // this step's ctx
            if (t + 1 < TT) mbar_expect_tx(h_mbar, DD * 4); // next phase's h
        }
        // prefetch this step's x-gate contribution
        const float xg = __ldg(XGb + t * 512 + ggate * DD + dcol);

        // ---------- P1: q = h @ Wa (regs) + hoisted h@U gate partial ----------
        float hu;
        {
            float accq = 0.f, huv = 0.f;
            #pragma unroll
            for (int kk = 0; kk < 64; kk++) accq += sh[qp + 2 * kk] * waReg[kk];
            #pragma unroll
            for (int kk = 0; kk < 32; kk++) huv += sh[gp + 4 * kk] * Ureg[kk];
            hu = huv;
            accq += __shfl_xor_sync(0xffffffffu, accq, 16);
            if (lane < 16) sq[(wp << 4) + lane] = accq;
        }
        __syncthreads();  // A

        // ---------- P2: scores (f16 HU + f16x2 tanh) -> exp -> ctx partial.
        //            no-max softmax: |score| <= sum|v| ~ 5. ----------
        {
            const float4 q4 = *reinterpret_cast<const float4*>(&sq[lane * 4]);
            const __half2 q01 = __floats2half2_rn(q4.x, q4.y);
            const __half2 q23 = __floats2half2_rn(q4.z, q4.w);
            float4 ctx4 = make_float4(0.f, 0.f, 0.f, 0.f);
            float zp = 0.f;
            #pragma unroll
            for (int i = 0; i < 8; i++) {
                const int s = wp + (i << 3);      // rows 0..63
                const uint2 hu2 = *reinterpret_cast<const uint2*>(sHUh + s * 64 + lane * 2);
                const __half2 a01 = __hadd2(*reinterpret_cast<const __half2*>(&hu2.x), q01);
                const __half2 a23 = __hadd2(*reinterpret_cast<const __half2*>(&hu2.y), q23);
                uint32_t t01, t23;
                asm("tanh.approx.f16x2 %0, %1;"
                    : "=r"(t01) : "r"(*reinterpret_cast<const uint32_t*>(&a01)));
                asm("tanh.approx.f16x2 %0, %1;"
                    : "=r"(t23) : "r"(*reinterpret_cast<const uint32_t*>(&a23)));
                const __half2 m = __hfma2(*reinterpret_cast<const __half2*>(&t01), v01,
                                  __hmul2(*reinterpret_cast<const __half2*>(&t23), v23));
                float sc = __low2float(m) + __high2float(m);
                #pragma unroll
                for (int o = 16; o > 0; o >>= 1) sc += __shfl_xor_sync(0xffffffffu, sc, o);
                const float e = __expf(sc);
                zp += e;
                const float4 h4 = *reinterpret_cast<const float4*>(&sHs[s * DD + lane * 4]);
                ctx4.x += e * h4.x; ctx4.y += e * h4.y;
                ctx4.z += e * h4.z; ctx4.w += e * h4.w;
            }
            *reinterpret_cast<float4*>(&part[wp * DD + lane * 4]) = ctx4;
            if (lane == 0) zred[wp] = zp;
        }
        __syncthreads();  // B

        // ---------- exchange: packed (ctx_r, z_r) -> all ranks ----------
        if (tid < DD) {
            float c = 0.f;
            #pragma unroll
            for (int w = 0; w < NWARP; w++) c += part[w * DD + tid];
            const float c1 = __shfl_down_sync(0xffffffffu, c, 1);
            const float c2 = __shfl_down_sync(0xffffffffu, c, 2);
            const float c3 = __shfl_down_sync(0xffffffffu, c, 3);
            if ((lane & 3) == 0) {
                #pragma unroll
                for (int q = 0; q < CLUSTER; q++)
                    st_async_remote_v4(ctx_addr, ctx_mbar, (uint32_t)q, c, c1, c2, c3);
            }
        } else if (wp == 4 && lane < 8) {
            // parallel z reduce (8-lane shuffle tree) + 8 parallel sends
            float zz = zred[lane];
            zz += __shfl_xor_sync(0x000000ffu, zz, 4);
            zz += __shfl_xor_sync(0x000000ffu, zz, 2);
            zz += __shfl_xor_sync(0x000000ffu, zz, 1);
            st_async_remote(zsl_addr, ctx_mbar, (uint32_t)lane, zz);
        }
        mbar_wait(ctx_mbar, parity);

        // ---------- combine: sctx = sum_r ctx_r (unnormalized); invZ once ----------
        if (tid < DD) {
            float c = 0.f;
            #pragma unroll
            for (int q = 0; q < CLUSTER; q++) c += ctxbuf[q * 132 + tid];
            sctx[tid] = c;
        } else if (tid == DD) {
            float Z = 0.f;
            #pragma unroll
            for (int q = 0; q < CLUSTER; q++) Z += ctxbuf[q * 132 + 128];
            s_invZ[0] = 1.f / Z;
        }
        __syncthreads();  // C

        // ---------- P4: all 4 gates for local d-slice; LOCAL LSTM update;
        //             h_new broadcast spread over 8 lanes per dim ----------
        {
            const float invZ = s_invZ[0];
            float acc = 0.f;
            #pragma unroll
            for (int kk = 0; kk < 32; kk++) acc += sctx[gp + 4 * kk] * Creg[kk];
            float p = hu + acc * invZ;
            p += __shfl_xor_sync(0xffffffffu, p, 1);
            p += __shfl_xor_sync(0xffffffffu, p, 2);
            const float pre = p + xg;
            const float act = (ggate == 2) ? tanhf(pre) : 1.f / (1.f + __expf(-pre));
            // gather the 4 gates of this half-warp's dim
            const int hb = lane & 16;
            const float ig = __shfl_sync(0xffffffffu, act, hb + 0);
            const float fg = __shfl_sync(0xffffffffu, act, hb + 4);
            const float gw = __shfl_sync(0xffffffffu, act, hb + 8);
            const float og = __shfl_sync(0xffffffffu, act, hb + 12);
            float hn = 0.f;
            if (h_owner) {
                cell = fg * cell + ig * gw;
                hn = og * tanhf(cell);
                out[(size_t)(b * TT + t) * DD + dme] = hn;
            }
            // spread send: shuffle executed by ALL lanes, then lanes {0..7}
            // and {16..23} each ship their group's hn to rank = lane&7
            const float hn_b = __shfl_sync(0xffffffffu, hn, lane & 16);
            if ((t + 1 < TT) && ((lane & 15) < 8))
                st_async_remote(h_addr, h_mbar, (uint32_t)(lane & 7), hn_b);
        }
        // no barrier here: next iteration's h_mbar wait orders everything.
    }

    // quiesce the cluster before any CTA retires (no in-flight remote writes)
    CLUSTER_SYNC();
}

// ---------------------------------------------------------------------------
extern "C" void kernel_launch(void* const* d_in, const int* in_sizes, int n_in,
                              void* d_out, int out_size) {
    const float* x    = (const float*)d_in[0];
    const float* H    = (const float*)d_in[1];
    const float* init = (const float*)d_in[2];
    const float* Wa   = (const float*)d_in[3];
    const float* Ua   = (const float*)d_in[4];
    const float* v    = (const float*)d_in[5];
    const float* Wi   = (const float*)d_in[6];
    const float* Ui   = (const float*)d_in[7];
    const float* Ci   = (const float*)d_in[8];
    const float* bi   = (const float*)d_in[9];
    const float* Wf   = (const float*)d_in[10];
    const float* Uf   = (const float*)d_in[11];
    const float* Cf   = (const float*)d_in[12];
    const float* bf   = (const float*)d_in[13];
    const float* Wc   = (const float*)d_in[14];
    const float* Uc   = (const float*)d_in[15];
    const float* Cc   = (const float*)d_in[16];
    const float* bc   = (const float*)d_in[17];
    const float* Wo   = (const float*)d_in[18];
    const float* Uo   = (const float*)d_in[19];
    const float* Co   = (const float*)d_in[20];
    const float* bo   = (const float*)d_in[21];
    float* out = (float*)d_out;

    static bool attr_set = false;
    if (!attr_set) {
        cudaFuncSetAttribute(rec_kernel,
                             cudaFuncAttributeMaxDynamicSharedMemorySize,
                             SM_FLOATS * sizeof(float));
        attr_set = true;
    }

    pre_kernel<<<1024, 128>>>(H, Ua, x, Wi, Wf, Wc, Wo, bi, bf, bc, bo);
    rec_kernel<<<BB * CLUSTER, NTHR, SM_FLOATS * sizeof(float)>>>(
        H, init, Wa, v, Ui, Ci, Uf, Cf, Uc, Cc, Uo, Co, out);
}